// round 11
// baseline (speedup 1.0000x reference)
#include <cuda_runtime.h>
#include <math.h>
#include <cstdint>

#define Bq   8
#define Nq   2048
#define Dq   1024
#define Eq   8
#define Hq   4096
#define CAP  320
#define NTOK (Bq*Nq)
#define OUT_MAIN ((size_t)NTOK*Dq)

// ---- scratch (round-5 set; no giant extra globals) ----
__device__ int   d_meta[NTOK];
__device__ float d_g1[NTOK];
__device__ float d_g2[NTOK];
__device__ int   d_a1[NTOK];
__device__ int   d_a2[NTOK];
__device__ float d_proxy[Bq*Eq];
__device__ int   d_slotTok[Eq*Bq*CAP];
__device__ float d_h [(size_t)Eq*Bq*CAP*Hq];   // tf32-valued post-GELU hidden
__device__ float d_eo[(size_t)Eq*Bq*CAP*Dq];

// ---------------- helpers ----------------
__device__ __forceinline__ uint32_t smem_u32(const void* p) {
    uint32_t a;
    asm("{ .reg .u64 t; cvta.to.shared.u64 t, %1; cvt.u32.u64 %0, t; }" : "=r"(a) : "l"(p));
    return a;
}
__device__ __forceinline__ uint32_t f2tf32(float x) {
    uint32_t r;
    asm("cvt.rna.tf32.f32 %0, %1;" : "=r"(r) : "f"(x));
    return r;
}
__device__ __forceinline__ float tf32v(float x) {
    return __uint_as_float(f2tf32(x));
}
__device__ __forceinline__ void mma_tf32(float* d, const uint32_t* a, const uint32_t* b) {
    asm volatile(
        "mma.sync.aligned.m16n8k8.row.col.f32.tf32.tf32.f32 "
        "{%0,%1,%2,%3}, {%4,%5,%6,%7}, {%8,%9}, {%0,%1,%2,%3};\n"
        : "+f"(d[0]), "+f"(d[1]), "+f"(d[2]), "+f"(d[3])
        : "r"(a[0]), "r"(a[1]), "r"(a[2]), "r"(a[3]), "r"(b[0]), "r"(b[1]));
}
__device__ __forceinline__ void ldsm4(uint32_t* r, uint32_t addr) {
    asm volatile("ldmatrix.sync.aligned.m8n8.x4.shared.b16 {%0,%1,%2,%3}, [%4];"
        : "=r"(r[0]), "=r"(r[1]), "=r"(r[2]), "=r"(r[3]) : "r"(addr));
}

// ---------------- init ----------------
__global__ void init_kernel() {
    int t = threadIdx.x;
    if (t < Bq*Eq) d_proxy[t] = 0.f;
}

// ---------------- gating ----------------
__global__ __launch_bounds__(256) void gating_kernel(
    const float* __restrict__ x, const float* __restrict__ wg,
    const float* __restrict__ rnd)
{
    __shared__ float s_wg[Eq][Dq];
    __shared__ float s_proxy[Eq];
    int tid = threadIdx.x;
    for (int f = tid; f < Dq*Eq; f += 256) {
        int d = f >> 3, e = f & 7;
        s_wg[e][d] = wg[f];
    }
    if (tid < Eq) s_proxy[tid] = 0.f;
    __syncthreads();

    int warp = tid >> 5, lane = tid & 31;
    int tok  = blockIdx.x * 8 + warp;
    const float* xp = x + (size_t)tok * Dq;

    float acc[Eq];
    #pragma unroll
    for (int e = 0; e < Eq; ++e) acc[e] = 0.f;
    #pragma unroll 4
    for (int i = 0; i < Dq/32; ++i) {
        float xv = xp[i*32 + lane];
        #pragma unroll
        for (int e = 0; e < Eq; ++e) acc[e] += xv * s_wg[e][i*32 + lane];
    }
    #pragma unroll
    for (int off = 16; off; off >>= 1)
        #pragma unroll
        for (int e = 0; e < Eq; ++e)
            acc[e] += __shfl_down_sync(0xffffffffu, acc[e], off);

    if (lane == 0) {
        float mx = acc[0];
        #pragma unroll
        for (int e = 1; e < Eq; ++e) mx = fmaxf(mx, acc[e]);
        float raw[Eq]; float s = 0.f;
        #pragma unroll
        for (int e = 0; e < Eq; ++e) { raw[e] = expf(acc[e] - mx); s += raw[e]; }
        float inv = 1.f / s;
        #pragma unroll
        for (int e = 0; e < Eq; ++e) raw[e] *= inv;
        int i1 = 0; float g1 = raw[0];
        #pragma unroll
        for (int e = 1; e < Eq; ++e) if (raw[e] > g1) { g1 = raw[e]; i1 = e; }
        int i2 = -1; float g2 = -1.f;
        #pragma unroll
        for (int e = 0; e < Eq; ++e) if (e != i1 && raw[e] > g2) { g2 = raw[e]; i2 = e; }
        float denom = g1 + g2 + 1e-9f;
        float g1n = g1 / denom, g2n = g2 / denom;
        int keep2 = (rnd[tok] < (g2n / 0.2f)) ? 1 : 0;
        d_meta[tok] = i1 | (i2 << 4) | (keep2 << 8);
        d_g1[tok] = g1n;
        d_g2[tok] = g2n;
        #pragma unroll
        for (int e = 0; e < Eq; ++e) atomicAdd(&s_proxy[e], raw[e]);
    }
    __syncthreads();
    if (tid < Eq) {
        int b = (blockIdx.x * 8) >> 11;
        atomicAdd(&d_proxy[b*Eq + tid], s_proxy[tid]);
    }
}

// ---------------- scan ----------------
__global__ void scan_kernel(float* __restrict__ dout, int out_size)
{
    __shared__ int   s_meta[2048];
    __shared__ float s_red[64];
    int t = threadIdx.x;
    int b = t >> 3, e = t & 7;
    int g = e * Bq + b;
    for (int j = 0; j < CAP; ++j) d_slotTok[g*CAP + j] = -1;
    int c1 = 0;
    for (int ch = 0; ch < 8; ++ch) {
        __syncthreads();
        for (int i = t; i < 2048; i += 64) {
            int bb = i >> 8, ii = i & 255;
            s_meta[i] = d_meta[bb*Nq + ch*256 + ii];
        }
        __syncthreads();
        for (int ii = 0; ii < 256; ++ii) {
            int meta = s_meta[b*256 + ii];
            if ((meta & 15) == e) {
                int n = ch*256 + ii;
                if (c1 < CAP) {
                    d_slotTok[g*CAP + c1] = n;
                    d_a1[b*Nq + n] = (e << 10) | c1;
                } else d_a1[b*Nq + n] = -1;
                c1++;
            }
        }
    }
    int c1raw = c1;
    int pos = (c1 < CAP) ? c1 : CAP;
    for (int ch = 0; ch < 8; ++ch) {
        __syncthreads();
        for (int i = t; i < 2048; i += 64) {
            int bb = i >> 8, ii = i & 255;
            s_meta[i] = d_meta[bb*Nq + ch*256 + ii];
        }
        __syncthreads();
        for (int ii = 0; ii < 256; ++ii) {
            int meta = s_meta[b*256 + ii];
            if (((meta >> 4) & 15) == e) {
                int n = ch*256 + ii;
                if ((meta >> 8) & 1) {
                    if (pos < CAP) {
                        d_slotTok[g*CAP + pos] = n;
                        d_a2[b*Nq + n] = (e << 10) | pos;
                    } else d_a2[b*Nq + n] = -1;
                    pos++;
                } else d_a2[b*Nq + n] = -1;
            }
        }
    }
    s_red[t] = (d_proxy[b*Eq + e] / (float)Nq) * ((float)c1raw / (float)Nq);
    __syncthreads();
    if (t == 0) {
        float s = 0.f;
        for (int i = 0; i < 64; ++i) s += s_red[i];
        if ((size_t)out_size > OUT_MAIN) dout[OUT_MAIN] = s * 0.01f;
    }
}

// ---------------- tf32 mma.sync grouped GEMM: 512 threads, warp tile 32x32 ----------------
// CTA 128x128, K in 32-chunks, 2-stage double buffer, 16 warps (4m x 4n).
// SMEM: sA[2][16384] @0 (A[row][k], off=row*128+16*(slot^(row&7)), slot=k/4)
//       sB[2][16384] @32768 (B[n][k], same swizzle)
//       sPtr @65536 (1KB), sBias @66560 (512B)
// Loaders: 512 threads -> per thread 2 float4 slots per operand per chunk.
#define SMEM_FFN 67072
#define FFN_THREADS 512

template<int PHASE>
__global__ __launch_bounds__(FFN_THREADS, 1) void ffn_mma(const float* __restrict__ X,
                                                          const float* __restrict__ W,
                                                          const float* __restrict__ Bias)
{
    constexpr int Kdim  = (PHASE == 1) ? Dq : Hq;
    constexpr int Ncols = (PHASE == 1) ? Hq : Dq;
    constexpr int NCH   = Kdim / 32;

    extern __shared__ char smem[];
    const float** sPtr  = (const float**)(smem + 65536);
    float*        sBias = (float*)(smem + 66560);

    const int tid  = threadIdx.x;
    const int wid  = tid >> 5, lane = tid & 31;
    const int g8   = lane >> 2, tg = lane & 3;
    const int n0   = blockIdx.x * 128;
    const int m0   = blockIdx.y * 128;
    const int grp  = blockIdx.z;
    const int e    = grp >> 3, b = grp & 7;
    const int wm   = wid & 3, wn = wid >> 2;       // 4m x 4n warps, 32x32 tiles
    const bool active = (m0 + wm*32) < CAP;        // skip all-padding 32-row slabs

    if (tid < 128) {
        int c = m0 + tid;
        const float* p = nullptr;
        if (c < CAP) {
            if (PHASE == 1) {
                int tok = d_slotTok[grp*CAP + c];
                if (tok >= 0) p = X + ((size_t)(b*Nq) + tok) * Dq;
            } else {
                p = d_h + ((size_t)grp*CAP + c) * Hq;
            }
        }
        sPtr[tid]  = p;
        sBias[tid] = Bias[(size_t)e * Ncols + n0 + tid];
    }
    __syncthreads();

    const uint32_t sb = smem_u32(smem);

    // A fill: row = tid>>2 (0..127), slots sbase, sbase+1 (sbase = (tid&3)*2)
    const int row   = tid >> 2;
    const int sbase = (tid & 3) * 2;
    const float* aRow = sPtr[row];
    uint32_t stRel[2];
    #pragma unroll
    for (int i = 0; i < 2; ++i)
        stRel[i] = (uint32_t)(row*128 + 16*((sbase + i) ^ (row & 7)));

    // B fill: bn = row, same slots; 4 scalar LDG per slot (k-strided at fixed n)
    const float* Wg = W + (size_t)e * Kdim * Ncols + n0;
    const int bn = row;

    float4 rA[2], rB[2];

    #define LDA(ch) do { \
        _Pragma("unroll") \
        for (int i = 0; i < 2; ++i) { \
            if (aRow) rA[i] = *(const float4*)(aRow + (ch)*32 + (sbase + i)*4); \
            else      rA[i] = make_float4(0.f, 0.f, 0.f, 0.f); \
        } } while (0)
    #define LDB(ch) do { \
        _Pragma("unroll") \
        for (int i = 0; i < 2; ++i) { \
            const float* wp = Wg + (size_t)((ch)*32 + (sbase + i)*4) * Ncols + bn; \
            rB[i].x = wp[0]; \
            rB[i].y = wp[Ncols]; \
            rB[i].z = wp[(size_t)2*Ncols]; \
            rB[i].w = wp[(size_t)3*Ncols]; \
        } } while (0)
    #define STA(buf) do { \
        _Pragma("unroll") \
        for (int i = 0; i < 2; ++i) { \
            float4 v = rA[i]; \
            if (PHASE == 1) { \
                v.x = tf32v(v.x); v.y = tf32v(v.y); \
                v.z = tf32v(v.z); v.w = tf32v(v.w); \
            } \
            *(float4*)(smem + (buf)*16384 + stRel[i]) = v; \
        } } while (0)
    #define STB(buf) do { \
        _Pragma("unroll") \
        for (int i = 0; i < 2; ++i) { \
            float4 v; \
            v.x = tf32v(rB[i].x); v.y = tf32v(rB[i].y); \
            v.z = tf32v(rB[i].z); v.w = tf32v(rB[i].w); \
            *(float4*)(smem + 32768 + (buf)*16384 + stRel[i]) = v; \
        } } while (0)

    // ldmatrix geometry (B identical to validated round-5; A rescaled to 32-row slabs)
    const int hiA = lane >> 4;
    const uint32_t aBase = sb + (uint32_t)(wm*32 + ((lane>>3)&1)*8 + (lane&7)) * 128u;
    const uint32_t bBase = sb + 32768u + (uint32_t)(wn*32 + (lane>>4)*8 + (lane&7)) * 128u;
    uint32_t aSw[4], bSw[4];
    #pragma unroll
    for (int ks = 0; ks < 4; ++ks) {
        aSw[ks] = 16u * (uint32_t)((2*ks + hiA) ^ (lane & 7));
        bSw[ks] = 16u * (uint32_t)((2*ks + ((lane>>3)&1)) ^ (lane & 7));
    }

    float acc[2][4][4];
    #pragma unroll
    for (int mi = 0; mi < 2; ++mi)
        #pragma unroll
        for (int ni = 0; ni < 4; ++ni)
            #pragma unroll
            for (int q = 0; q < 4; ++q) acc[mi][ni][q] = 0.f;

    LDA(0); LDB(0);
    STA(0); STB(0);
    __syncthreads();

    for (int ch = 0; ch < NCH; ++ch) {
        const uint32_t bufOff = (ch & 1) ? 16384u : 0u;
        if (ch + 1 < NCH) { LDA(ch + 1); LDB(ch + 1); }

        if (active) {
            #pragma unroll
            for (int ks = 0; ks < 4; ++ks) {
                uint32_t af[2][4], bf[2][4];
                const uint32_t ao = bufOff + aSw[ks];
                const uint32_t bo = bufOff + bSw[ks];
                ldsm4(af[0], aBase + ao);
                ldsm4(af[1], aBase + 2048u + ao);
                ldsm4(bf[0], bBase + bo);
                ldsm4(bf[1], bBase + 2048u + bo);
                #pragma unroll
                for (int mi = 0; mi < 2; ++mi) {
                    mma_tf32(acc[mi][0], af[mi], &bf[0][0]);
                    mma_tf32(acc[mi][1], af[mi], &bf[0][2]);
                    mma_tf32(acc[mi][2], af[mi], &bf[1][0]);
                    mma_tf32(acc[mi][3], af[mi], &bf[1][2]);
                }
            }
        }

        if (ch + 1 < NCH) { STA((ch + 1) & 1); STB((ch + 1) & 1); }
        __syncthreads();
    }
    #undef LDA
    #undef LDB
    #undef STA
    #undef STB

    // epilogue: bias (+GELU phase1, tf32-round d_h so phase2 skips A-side cvt)
    float* Outp = (PHASE == 1) ? d_h : d_eo;
    #pragma unroll
    for (int mi = 0; mi < 2; ++mi) {
        #pragma unroll
        for (int h = 0; h < 2; ++h) {
            int c = m0 + wm*32 + mi*16 + g8 + h*8;
            if (c < CAP) {
                float* orow = Outp + ((size_t)grp*CAP + c) * Ncols + n0;
                #pragma unroll
                for (int ni = 0; ni < 4; ++ni) {
                    int col = wn*32 + ni*8 + 2*tg;
                    float v0 = acc[mi][ni][2*h]     + sBias[col];
                    float v1 = acc[mi][ni][2*h + 1] + sBias[col + 1];
                    if (PHASE == 1) {
                        v0 = 0.5f * v0 * (1.0f + erff(v0 * 0.70710678118654752f));
                        v1 = 0.5f * v1 * (1.0f + erff(v1 * 0.70710678118654752f));
                        v0 = tf32v(v0);
                        v1 = tf32v(v1);
                    }
                    float2 v = make_float2(v0, v1);
                    *(float2*)(orow + col) = v;
                }
            }
        }
    }
}

// ---------------- combine ----------------
__global__ __launch_bounds__(256) void combine_kernel(float* __restrict__ out)
{
    int tok = blockIdx.x;
    int b   = tok >> 11;
    int a1  = d_a1[tok], a2 = d_a2[tok];
    float g1 = d_g1[tok], g2 = d_g2[tok];
    int off = threadIdx.x * 4;

    float4 v = make_float4(0.f, 0.f, 0.f, 0.f);
    if (a1 >= 0) {
        size_t row = ((size_t)((a1 >> 10) * Bq + b)) * CAP + (a1 & 1023);
        const float4 s = *(const float4*)(d_eo + row * Dq + off);
        v.x = g1 * s.x; v.y = g1 * s.y; v.z = g1 * s.z; v.w = g1 * s.w;
    }
    if (a2 >= 0) {
        size_t row = ((size_t)((a2 >> 10) * Bq + b)) * CAP + (a2 & 1023);
        const float4 s = *(const float4*)(d_eo + row * Dq + off);
        v.x += g2 * s.x; v.y += g2 * s.y; v.z += g2 * s.z; v.w += g2 * s.w;
    }
    *(float4*)(out + (size_t)tok * Dq + off) = v;
}

// ---------------- launch ----------------
extern "C" void kernel_launch(void* const* d_in, const int* in_sizes, int n_in,
                              void* d_out, int out_size)
{
    const float* x  = (const float*)d_in[0];
    const float* wg = (const float*)d_in[1];
    const float* w1 = (const float*)d_in[2];
    const float* b1 = (const float*)d_in[3];
    const float* w2 = (const float*)d_in[4];
    const float* b2 = (const float*)d_in[5];
    const float* rp = (const float*)d_in[6];
    float* out = (float*)d_out;

    cudaFuncSetAttribute(ffn_mma<1>, cudaFuncAttributeMaxDynamicSharedMemorySize, SMEM_FFN);
    cudaFuncSetAttribute(ffn_mma<2>, cudaFuncAttributeMaxDynamicSharedMemorySize, SMEM_FFN);

    init_kernel<<<1, 64>>>();
    gating_kernel<<<NTOK/8, 256>>>(x, wg, rp);
    scan_kernel<<<1, 64>>>(out, out_size);

    ffn_mma<1><<<dim3(Hq/128, 3, Eq*Bq), FFN_THREADS, SMEM_FFN>>>(x, w1, b1);
    ffn_mma<2><<<dim3(Dq/128, 3, Eq*Bq), FFN_THREADS, SMEM_FFN>>>(d_h, w2, b2);

    combine_kernel<<<NTOK, 256>>>(out);
}

// round 12
// speedup vs baseline: 1.2739x; 1.2739x over previous
#include <cuda_runtime.h>
#include <math.h>
#include <cstdint>

#define Bq   8
#define Nq   2048
#define Dq   1024
#define Eq   8
#define Hq   4096
#define CAP  320
#define NTOK (Bq*Nq)
#define OUT_MAIN ((size_t)NTOK*Dq)

// ---- scratch (round-5 set; no giant extra globals) ----
__device__ int   d_meta[NTOK];
__device__ float d_g1[NTOK];
__device__ float d_g2[NTOK];
__device__ int   d_a1[NTOK];
__device__ int   d_a2[NTOK];
__device__ float d_proxy[Bq*Eq];
__device__ int   d_slotTok[Eq*Bq*CAP];
__device__ float d_h [(size_t)Eq*Bq*CAP*Hq];   // tf32-valued post-GELU hidden
__device__ float d_eo[(size_t)Eq*Bq*CAP*Dq];

// ---------------- helpers ----------------
__device__ __forceinline__ uint32_t smem_u32(const void* p) {
    uint32_t a;
    asm("{ .reg .u64 t; cvta.to.shared.u64 t, %1; cvt.u32.u64 %0, t; }" : "=r"(a) : "l"(p));
    return a;
}
__device__ __forceinline__ uint32_t f2tf32(float x) {
    uint32_t r;
    asm("cvt.rna.tf32.f32 %0, %1;" : "=r"(r) : "f"(x));
    return r;
}
__device__ __forceinline__ float tf32v(float x) {
    return __uint_as_float(f2tf32(x));
}
__device__ __forceinline__ void mma_tf32(float* d, const uint32_t* a, const uint32_t* b) {
    asm volatile(
        "mma.sync.aligned.m16n8k8.row.col.f32.tf32.tf32.f32 "
        "{%0,%1,%2,%3}, {%4,%5,%6,%7}, {%8,%9}, {%0,%1,%2,%3};\n"
        : "+f"(d[0]), "+f"(d[1]), "+f"(d[2]), "+f"(d[3])
        : "r"(a[0]), "r"(a[1]), "r"(a[2]), "r"(a[3]), "r"(b[0]), "r"(b[1]));
}
__device__ __forceinline__ void ldsm4(uint32_t* r, uint32_t addr) {
    asm volatile("ldmatrix.sync.aligned.m8n8.x4.shared.b16 {%0,%1,%2,%3}, [%4];"
        : "=r"(r[0]), "=r"(r[1]), "=r"(r[2]), "=r"(r[3]) : "r"(addr));
}

// ---------------- init ----------------
__global__ void init_kernel() {
    int t = threadIdx.x;
    if (t < Bq*Eq) d_proxy[t] = 0.f;
}

// ---------------- gating ----------------
__global__ __launch_bounds__(256) void gating_kernel(
    const float* __restrict__ x, const float* __restrict__ wg,
    const float* __restrict__ rnd)
{
    __shared__ float s_wg[Eq][Dq];
    __shared__ float s_proxy[Eq];
    int tid = threadIdx.x;
    for (int f = tid; f < Dq*Eq; f += 256) {
        int d = f >> 3, e = f & 7;
        s_wg[e][d] = wg[f];
    }
    if (tid < Eq) s_proxy[tid] = 0.f;
    __syncthreads();

    int warp = tid >> 5, lane = tid & 31;
    int tok  = blockIdx.x * 8 + warp;
    const float* xp = x + (size_t)tok * Dq;

    float acc[Eq];
    #pragma unroll
    for (int e = 0; e < Eq; ++e) acc[e] = 0.f;
    #pragma unroll 4
    for (int i = 0; i < Dq/32; ++i) {
        float xv = xp[i*32 + lane];
        #pragma unroll
        for (int e = 0; e < Eq; ++e) acc[e] += xv * s_wg[e][i*32 + lane];
    }
    #pragma unroll
    for (int off = 16; off; off >>= 1)
        #pragma unroll
        for (int e = 0; e < Eq; ++e)
            acc[e] += __shfl_down_sync(0xffffffffu, acc[e], off);

    if (lane == 0) {
        float mx = acc[0];
        #pragma unroll
        for (int e = 1; e < Eq; ++e) mx = fmaxf(mx, acc[e]);
        float raw[Eq]; float s = 0.f;
        #pragma unroll
        for (int e = 0; e < Eq; ++e) { raw[e] = expf(acc[e] - mx); s += raw[e]; }
        float inv = 1.f / s;
        #pragma unroll
        for (int e = 0; e < Eq; ++e) raw[e] *= inv;
        int i1 = 0; float g1 = raw[0];
        #pragma unroll
        for (int e = 1; e < Eq; ++e) if (raw[e] > g1) { g1 = raw[e]; i1 = e; }
        int i2 = -1; float g2 = -1.f;
        #pragma unroll
        for (int e = 0; e < Eq; ++e) if (e != i1 && raw[e] > g2) { g2 = raw[e]; i2 = e; }
        float denom = g1 + g2 + 1e-9f;
        float g1n = g1 / denom, g2n = g2 / denom;
        int keep2 = (rnd[tok] < (g2n / 0.2f)) ? 1 : 0;
        d_meta[tok] = i1 | (i2 << 4) | (keep2 << 8);
        d_g1[tok] = g1n;
        d_g2[tok] = g2n;
        #pragma unroll
        for (int e = 0; e < Eq; ++e) atomicAdd(&s_proxy[e], raw[e]);
    }
    __syncthreads();
    if (tid < Eq) {
        int b = (blockIdx.x * 8) >> 11;
        atomicAdd(&d_proxy[b*Eq + tid], s_proxy[tid]);
    }
}

// ---------------- scan ----------------
__global__ void scan_kernel(float* __restrict__ dout, int out_size)
{
    __shared__ int   s_meta[2048];
    __shared__ float s_red[64];
    int t = threadIdx.x;
    int b = t >> 3, e = t & 7;
    int g = e * Bq + b;
    for (int j = 0; j < CAP; ++j) d_slotTok[g*CAP + j] = -1;
    int c1 = 0;
    for (int ch = 0; ch < 8; ++ch) {
        __syncthreads();
        for (int i = t; i < 2048; i += 64) {
            int bb = i >> 8, ii = i & 255;
            s_meta[i] = d_meta[bb*Nq + ch*256 + ii];
        }
        __syncthreads();
        for (int ii = 0; ii < 256; ++ii) {
            int meta = s_meta[b*256 + ii];
            if ((meta & 15) == e) {
                int n = ch*256 + ii;
                if (c1 < CAP) {
                    d_slotTok[g*CAP + c1] = n;
                    d_a1[b*Nq + n] = (e << 10) | c1;
                } else d_a1[b*Nq + n] = -1;
                c1++;
            }
        }
    }
    int c1raw = c1;
    int pos = (c1 < CAP) ? c1 : CAP;
    for (int ch = 0; ch < 8; ++ch) {
        __syncthreads();
        for (int i = t; i < 2048; i += 64) {
            int bb = i >> 8, ii = i & 255;
            s_meta[i] = d_meta[bb*Nq + ch*256 + ii];
        }
        __syncthreads();
        for (int ii = 0; ii < 256; ++ii) {
            int meta = s_meta[b*256 + ii];
            if (((meta >> 4) & 15) == e) {
                int n = ch*256 + ii;
                if ((meta >> 8) & 1) {
                    if (pos < CAP) {
                        d_slotTok[g*CAP + pos] = n;
                        d_a2[b*Nq + n] = (e << 10) | pos;
                    } else d_a2[b*Nq + n] = -1;
                    pos++;
                } else d_a2[b*Nq + n] = -1;
            }
        }
    }
    s_red[t] = (d_proxy[b*Eq + e] / (float)Nq) * ((float)c1raw / (float)Nq);
    __syncthreads();
    if (t == 0) {
        float s = 0.f;
        for (int i = 0; i < 64; ++i) s += s_red[i];
        if ((size_t)out_size > OUT_MAIN) dout[OUT_MAIN] = s * 0.01f;
    }
}

// ---------------- tf32 mma.sync grouped GEMM: CTA 128x256, warp tile 64x64 ----------------
// 8 warps (2m x 4n), K in 32-chunks, 2-stage double buffer.
// SMEM: sA[2][16384] @0        (A[row(128)][k(32)], off=row*128+16*(slot^(row&7)))
//       sB[2][32768] @32768    (B[n(256)][k(32)],  same swizzle)
//       sPtr @98304 (1KB), sBias @99328 (1KB)  -> total 100352
// Loaders (256 thr): A 4 x f4/thread (row=tid>>1, slots (tid&1)*4+0..3),
//                    B 8 x f4/thread (bn=tid, slots 0..7; 4 coalesced scalar LDG each).
#define SMEM_FFN 100352
#define FFN_THREADS 256

template<int PHASE>
__global__ __launch_bounds__(FFN_THREADS, 1) void ffn_mma(const float* __restrict__ X,
                                                          const float* __restrict__ W,
                                                          const float* __restrict__ Bias)
{
    constexpr int Kdim  = (PHASE == 1) ? Dq : Hq;
    constexpr int Ncols = (PHASE == 1) ? Hq : Dq;
    constexpr int NCH   = Kdim / 32;

    extern __shared__ char smem[];
    const float** sPtr  = (const float**)(smem + 98304);
    float*        sBias = (float*)(smem + 99328);

    const int tid  = threadIdx.x;
    const int wid  = tid >> 5, lane = tid & 31;
    const int g8   = lane >> 2, tg = lane & 3;
    const int n0   = blockIdx.x * 256;
    const int m0   = blockIdx.y * 128;
    const int grp  = blockIdx.z;
    const int e    = grp >> 3, b = grp & 7;
    const int wm   = wid & 1, wn = wid >> 1;       // 2m x 4n warps, 64x64 tiles
    const bool active = (m0 + wm*64) < CAP;        // skip all-padding 64-row slabs

    if (tid < 128) {
        int c = m0 + tid;
        const float* p = nullptr;
        if (c < CAP) {
            if (PHASE == 1) {
                int tok = d_slotTok[grp*CAP + c];
                if (tok >= 0) p = X + ((size_t)(b*Nq) + tok) * Dq;
            } else {
                p = d_h + ((size_t)grp*CAP + c) * Hq;
            }
        }
        sPtr[tid] = p;
    }
    sBias[tid] = Bias[(size_t)e * Ncols + n0 + tid];
    __syncthreads();

    const uint32_t sb = smem_u32(smem);

    // A fill: row = tid>>1 (0..127), slots sbase..sbase+3 (sbase = (tid&1)*4)
    const int row   = tid >> 1;
    const int sbase = (tid & 1) * 4;
    const float* aRow = sPtr[row];
    uint32_t stRelA[4];
    #pragma unroll
    for (int i = 0; i < 4; ++i)
        stRelA[i] = (uint32_t)(row*128 + 16*((sbase + i) ^ (row & 7)));

    // B fill: bn = tid (0..255), slots 0..7
    const int bn = tid;
    const float* Wg = W + (size_t)e * Kdim * Ncols + n0;
    uint32_t stRelB[8];
    #pragma unroll
    for (int s = 0; s < 8; ++s)
        stRelB[s] = (uint32_t)(bn*128 + 16*(s ^ (bn & 7)));

    float4 rA[4], rB[8];

    #define LDA(ch) do { \
        _Pragma("unroll") \
        for (int i = 0; i < 4; ++i) { \
            if (aRow) rA[i] = *(const float4*)(aRow + (ch)*32 + (sbase + i)*4); \
            else      rA[i] = make_float4(0.f, 0.f, 0.f, 0.f); \
        } } while (0)
    #define LDB(ch) do { \
        _Pragma("unroll") \
        for (int s = 0; s < 8; ++s) { \
            const float* wp = Wg + (size_t)((ch)*32 + s*4) * Ncols + bn; \
            rB[s].x = wp[0]; \
            rB[s].y = wp[Ncols]; \
            rB[s].z = wp[(size_t)2*Ncols]; \
            rB[s].w = wp[(size_t)3*Ncols]; \
        } } while (0)
    #define STA(buf) do { \
        _Pragma("unroll") \
        for (int i = 0; i < 4; ++i) { \
            float4 v = rA[i]; \
            if (PHASE == 1) { \
                v.x = tf32v(v.x); v.y = tf32v(v.y); \
                v.z = tf32v(v.z); v.w = tf32v(v.w); \
            } \
            *(float4*)(smem + (buf)*16384 + stRelA[i]) = v; \
        } } while (0)
    #define STB(buf) do { \
        _Pragma("unroll") \
        for (int s = 0; s < 8; ++s) { \
            float4 v; \
            v.x = tf32v(rB[s].x); v.y = tf32v(rB[s].y); \
            v.z = tf32v(rB[s].z); v.w = tf32v(rB[s].w); \
            *(float4*)(smem + 32768 + (buf)*32768 + stRelB[s]) = v; \
        } } while (0)

    // ldmatrix geometry (A identical to r10; B same pattern over 64-row slab)
    const int hiA = lane >> 4;
    const uint32_t aBaseRel = (uint32_t)(wm*64 + ((lane>>3)&1)*8 + (lane&7)) * 128u;
    const uint32_t bBaseRel = (uint32_t)(wn*64 + (lane>>4)*8 + (lane&7)) * 128u;
    uint32_t aSw[4], bSw[4];
    #pragma unroll
    for (int ks = 0; ks < 4; ++ks) {
        aSw[ks] = 16u * (uint32_t)((2*ks + hiA) ^ (lane & 7));
        bSw[ks] = 16u * (uint32_t)((2*ks + ((lane>>3)&1)) ^ (lane & 7));
    }

    float acc[4][8][4];
    #pragma unroll
    for (int mi = 0; mi < 4; ++mi)
        #pragma unroll
        for (int ni = 0; ni < 8; ++ni)
            #pragma unroll
            for (int q = 0; q < 4; ++q) acc[mi][ni][q] = 0.f;

    LDA(0); LDB(0);
    STA(0); STB(0);
    __syncthreads();

    for (int ch = 0; ch < NCH; ++ch) {
        const int buf = ch & 1;
        if (ch + 1 < NCH) { LDA(ch + 1); LDB(ch + 1); }

        if (active) {
            const uint32_t aOff = sb + (uint32_t)(buf*16384);
            const uint32_t bOff = sb + 32768u + (uint32_t)(buf*32768);
            #pragma unroll
            for (int ks = 0; ks < 4; ++ks) {
                uint32_t af[4][4], bf[4][4];
                const uint32_t ao = aOff + aBaseRel + aSw[ks];
                const uint32_t bo = bOff + bBaseRel + bSw[ks];
                #pragma unroll
                for (int mi = 0; mi < 4; ++mi)
                    ldsm4(af[mi], ao + (uint32_t)(mi*2048));
                #pragma unroll
                for (int j = 0; j < 4; ++j)
                    ldsm4(bf[j], bo + (uint32_t)(j*2048));
                #pragma unroll
                for (int mi = 0; mi < 4; ++mi)
                    #pragma unroll
                    for (int j = 0; j < 4; ++j) {
                        mma_tf32(acc[mi][2*j],     af[mi], &bf[j][0]);
                        mma_tf32(acc[mi][2*j + 1], af[mi], &bf[j][2]);
                    }
            }
        }

        if (ch + 1 < NCH) { STA((ch + 1) & 1); STB((ch + 1) & 1); }
        __syncthreads();
    }
    #undef LDA
    #undef LDB
    #undef STA
    #undef STB

    // epilogue: bias (+GELU phase1, tf32-round d_h so phase2 skips A-side cvt)
    float* Outp = (PHASE == 1) ? d_h : d_eo;
    #pragma unroll
    for (int mi = 0; mi < 4; ++mi) {
        #pragma unroll
        for (int h = 0; h < 2; ++h) {
            int c = m0 + wm*64 + mi*16 + g8 + h*8;
            if (c < CAP) {
                float* orow = Outp + ((size_t)grp*CAP + c) * Ncols + n0;
                #pragma unroll
                for (int ni = 0; ni < 8; ++ni) {
                    int col = wn*64 + ni*8 + 2*tg;
                    float v0 = acc[mi][ni][2*h]     + sBias[col];
                    float v1 = acc[mi][ni][2*h + 1] + sBias[col + 1];
                    if (PHASE == 1) {
                        v0 = 0.5f * v0 * (1.0f + erff(v0 * 0.70710678118654752f));
                        v1 = 0.5f * v1 * (1.0f + erff(v1 * 0.70710678118654752f));
                        v0 = tf32v(v0);
                        v1 = tf32v(v1);
                    }
                    float2 v = make_float2(v0, v1);
                    *(float2*)(orow + col) = v;
                }
            }
        }
    }
}

// ---------------- combine ----------------
__global__ __launch_bounds__(256) void combine_kernel(float* __restrict__ out)
{
    int tok = blockIdx.x;
    int b   = tok >> 11;
    int a1  = d_a1[tok], a2 = d_a2[tok];
    float g1 = d_g1[tok], g2 = d_g2[tok];
    int off = threadIdx.x * 4;

    float4 v = make_float4(0.f, 0.f, 0.f, 0.f);
    if (a1 >= 0) {
        size_t row = ((size_t)((a1 >> 10) * Bq + b)) * CAP + (a1 & 1023);
        const float4 s = *(const float4*)(d_eo + row * Dq + off);
        v.x = g1 * s.x; v.y = g1 * s.y; v.z = g1 * s.z; v.w = g1 * s.w;
    }
    if (a2 >= 0) {
        size_t row = ((size_t)((a2 >> 10) * Bq + b)) * CAP + (a2 & 1023);
        const float4 s = *(const float4*)(d_eo + row * Dq + off);
        v.x += g2 * s.x; v.y += g2 * s.y; v.z += g2 * s.z; v.w += g2 * s.w;
    }
    *(float4*)(out + (size_t)tok * Dq + off) = v;
}

// ---------------- launch ----------------
extern "C" void kernel_launch(void* const* d_in, const int* in_sizes, int n_in,
                              void* d_out, int out_size)
{
    const float* x  = (const float*)d_in[0];
    const float* wg = (const float*)d_in[1];
    const float* w1 = (const float*)d_in[2];
    const float* b1 = (const float*)d_in[3];
    const float* w2 = (const float*)d_in[4];
    const float* b2 = (const float*)d_in[5];
    const float* rp = (const float*)d_in[6];
    float* out = (float*)d_out;

    cudaFuncSetAttribute(ffn_mma<1>, cudaFuncAttributeMaxDynamicSharedMemorySize, SMEM_FFN);
    cudaFuncSetAttribute(ffn_mma<2>, cudaFuncAttributeMaxDynamicSharedMemorySize, SMEM_FFN);

    init_kernel<<<1, 64>>>();
    gating_kernel<<<NTOK/8, 256>>>(x, wg, rp);
    scan_kernel<<<1, 64>>>(out, out_size);

    ffn_mma<1><<<dim3(Hq/256, 3, Eq*Bq), FFN_THREADS, SMEM_FFN>>>(x, w1, b1);
    ffn_mma<2><<<dim3(Dq/256, 3, Eq*Bq), FFN_THREADS, SMEM_FFN>>>(d_h, w2, b2);

    combine_kernel<<<NTOK, 256>>>(out);
}